// round 5
// baseline (speedup 1.0000x reference)
#include <cuda_runtime.h>
#include <cuda_bf16.h>
#include <math.h>
#include <stdint.h>

#define TT   512
#define BB   64
#define DD   1024
#define NBK  16
#define TOKN (TT*BB)                 // 32768
#define CAP  8192
#define NLIST (NBK*CAP)
#define OUT_OFF ((size_t)TOKN*64)
#define NKTI (DD/16)                 // 64 k-tiles of 16

// ---------------- scratch ---------------------------------------------------
__device__ float    g_logits[TOKN*NBK];
__device__ float    g_q[(size_t)TOKN*64];
__device__ float    g_w[TOKN*NBK];
__device__ int      g_sel[TOKN*2];
__device__ float    g_selout[(size_t)TOKN*2*192];
__device__ float    g_partial[(size_t)TOKN*NBK*64];
__device__ unsigned g_list[NLIST];
__device__ int      g_cursor[NBK];
// fragment-shuffled hi/lo bf16 packs: unit (row, kti, j) = (h_j, h_{j+4}, l_j, l_{j+4})
__device__ uint4    g_xpack[(size_t)TOKN*NKTI*4];        // 128 MB
__device__ uint4    g_wpack[(size_t)NBK*192*NKTI*4];     // 12.6 MB

// ---------------- fast math --------------------------------------------------
__device__ __forceinline__ float ex2a(float x){ float r; asm("ex2.approx.f32 %0,%1;":"=f"(r):"f"(x)); return r; }
__device__ __forceinline__ float rcpa(float x){ float r; asm("rcp.approx.f32 %0,%1;":"=f"(r):"f"(x)); return r; }
__device__ __forceinline__ float fast_rcp(float z){ float y = rcpa(z); return y * fmaf(-z, y, 2.0f); }
__device__ __forceinline__ float fsig(float x){ float E = ex2a(-1.44269504f * x); return fast_rcp(1.0f + E); }
__device__ __forceinline__ float ftanh(float x){ float E = ex2a(2.88539008f * x); return fmaf(-2.0f, fast_rcp(1.0f + E), 1.0f); }

__device__ __forceinline__ uint32_t f2tf(float f){ uint32_t r; asm("cvt.rna.tf32.f32 %0,%1;":"=r"(r):"f"(f)); return r; }
__device__ __forceinline__ uint32_t bf16r(float f){ uint16_t r; asm("cvt.rn.bf16.f32 %0,%1;":"=h"(r):"f"(f)); return (uint32_t)r; }
__device__ __forceinline__ void split_pack(float a, float b, uint32_t &hi, uint32_t &lo){
    uint32_t ha = bf16r(a), hb = bf16r(b);
    float ra = a - __uint_as_float(ha << 16);
    float rb = b - __uint_as_float(hb << 16);
    hi = ha | (hb << 16);
    lo = bf16r(ra) | (bf16r(rb) << 16);
}

__device__ __forceinline__ void mma_tf32(float4 &d, const uint4 &a, const uint2 &b){
    asm volatile("mma.sync.aligned.m16n8k8.row.col.f32.tf32.tf32.f32 "
                 "{%0,%1,%2,%3},{%4,%5,%6,%7},{%8,%9},{%0,%1,%2,%3};"
                 : "+f"(d.x), "+f"(d.y), "+f"(d.z), "+f"(d.w)
                 : "r"(a.x), "r"(a.y), "r"(a.z), "r"(a.w), "r"(b.x), "r"(b.y));
}
__device__ __forceinline__ void mma_bf16(float4 &d, uint32_t a0, uint32_t a1, uint32_t a2, uint32_t a3,
                                         uint32_t b0, uint32_t b1){
    asm volatile("mma.sync.aligned.m16n8k16.row.col.f32.bf16.bf16.f32 "
                 "{%0,%1,%2,%3},{%4,%5,%6,%7},{%8,%9},{%0,%1,%2,%3};"
                 : "+f"(d.x), "+f"(d.y), "+f"(d.z), "+f"(d.w)
                 : "r"(a0), "r"(a1), "r"(a2), "r"(a3), "r"(b0), "r"(b1));
}

__device__ __forceinline__ void cpa16(uint32_t dst, const void* src){
    asm volatile("cp.async.cg.shared.global [%0], [%1], 16;\n" :: "r"(dst), "l"(src));
}
__device__ __forceinline__ void cpa_commit(){ asm volatile("cp.async.commit_group;\n"); }
template<int N> __device__ __forceinline__ void cpa_wait(){ asm volatile("cp.async.wait_group %0;\n"::"n"(N)); }

// ---------------- K0: prep — list init + X/W split-pack conversion -----------
// blocks [0, 32768): X row conversion; [32768, 35840): W rows; [35840, 36352): init
__global__ __launch_bounds__(256) void k_prep(const float* __restrict__ x,
                                              const float* __restrict__ Wkv,
                                              const float* __restrict__ Wbeta) {
    const int bid = blockIdx.x, tid = threadIdx.x;
    const int kti = tid >> 2, j = tid & 3;
    if (bid < TOKN) {
        const float* src = x + (size_t)bid * DD + kti * 16 + 2 * j;
        float2 v0 = *(const float2*)src;
        float2 v1 = *(const float2*)(src + 8);
        uint32_t h0, l0, h1, l1;
        split_pack(v0.x, v0.y, h0, l0);
        split_pack(v1.x, v1.y, h1, l1);
        g_xpack[(size_t)bid * 256 + tid] = make_uint4(h0, h1, l0, l1);
    } else if (bid < TOKN + NBK * 192) {
        int R = bid - TOKN;
        int e = R / 192, n = R % 192;
        const float* base = (n < 128) ? (Wkv + ((size_t)e * 128 + n) * DD)
                                      : (Wbeta + ((size_t)e * 64 + (n - 128)) * DD);
        const float* src = base + kti * 16 + 2 * j;
        float2 v0 = *(const float2*)src;
        float2 v1 = *(const float2*)(src + 8);
        uint32_t h0, l0, h1, l1;
        split_pack(v0.x, v0.y, h0, l0);
        split_pack(v1.x, v1.y, h1, l1);
        g_wpack[(size_t)R * 256 + tid] = make_uint4(h0, h1, l0, l1);
    } else {
        int i = (bid - (TOKN + NBK * 192)) * 256 + tid;
        if (i < NLIST) g_list[i] = 0xFFFFFFFFu;
        if (i < NBK)   g_cursor[i] = i * CAP;
    }
}

// ---------------- K1: router+q GEMM via tf32 3-split mma ---------------------
__global__ __launch_bounds__(256) void k_rq_mma(const float* __restrict__ x,
                                                const float* __restrict__ Wr,
                                                const float* __restrict__ Wq) {
    __shared__ uint32_t Ah[4*2*32*4], Al[4*2*32*4];
    __shared__ uint32_t Bh[10*2*32*2], Bl[10*2*32*2];

    const int tid = threadIdx.x;
    const int row0 = blockIdx.x * 64;
    const int warp = tid >> 5, lane = tid & 31;
    const int wm = warp >> 1, wn = warp & 1;

    float4 acc[5];
#pragma unroll
    for (int j = 0; j < 5; j++) acc[j] = make_float4(0.f, 0.f, 0.f, 0.f);

    const int xrow = tid >> 2, xk0 = (tid & 3) * 4;
    const float* xp = x + (size_t)(row0 + xrow) * DD + xk0;
    const int xs = xk0 >> 3;
    const int xreg = ((xk0 & 4) ? 2 : 0) + (((xrow & 15) >= 8) ? 1 : 0);
    const int xbase = ((((xrow >> 4) * 2 + xs) * 32 + ((xrow & 7) << 2)) << 2) + xreg;

    for (int kt = 0; kt < DD; kt += 16) {
        {
            float4 v = *(const float4*)(xp + kt);
            float vv[4] = {v.x, v.y, v.z, v.w};
#pragma unroll
            for (int j = 0; j < 4; j++) {
                uint32_t h = f2tf(vv[j]);
                Ah[xbase + (j << 2)] = h;
                Al[xbase + (j << 2)] = f2tf(vv[j] - __uint_as_float(h));
            }
        }
#pragma unroll
        for (int it = 0; it < 2; it++) {
            int fi = tid + it * 256;
            if (fi < 320) {
                int row = fi >> 2, k0 = (fi & 3) * 4;
                const float* wp = (row < 16) ? (Wr + (size_t)row * DD)
                                             : (Wq + (size_t)(row - 16) * DD);
                float4 v = *(const float4*)(wp + kt + k0);
                int s = k0 >> 3, reg = (k0 & 4) ? 1 : 0;
                int base = ((((row >> 3) * 2 + s) * 32 + ((row & 7) << 2)) << 1) + reg;
                float vv[4] = {v.x, v.y, v.z, v.w};
#pragma unroll
                for (int j = 0; j < 4; j++) {
                    uint32_t h = f2tf(vv[j]);
                    Bh[base + (j << 1)] = h;
                    Bl[base + (j << 1)] = f2tf(vv[j] - __uint_as_float(h));
                }
            }
        }
        __syncthreads();
#pragma unroll
        for (int s = 0; s < 2; s++) {
            int aidx = (((wm * 2 + s) * 32 + lane) << 2);
            uint4 ah = *(const uint4*)&Ah[aidx];
            uint4 al = *(const uint4*)&Al[aidx];
#pragma unroll
            for (int ni = 0; ni < 5; ni++) {
                int bidx = ((((wn * 5 + ni) * 2 + s) * 32 + lane) << 1);
                uint2 bh = *(const uint2*)&Bh[bidx];
                uint2 bl = *(const uint2*)&Bl[bidx];
                mma_tf32(acc[ni], ah, bh);
                mma_tf32(acc[ni], ah, bl);
                mma_tf32(acc[ni], al, bh);
            }
        }
        __syncthreads();
    }
    int r0 = row0 + wm * 16 + (lane >> 2);
#pragma unroll
    for (int ni = 0; ni < 5; ni++) {
        int c0 = wn * 40 + ni * 8 + ((lane & 3) << 1);
        if (c0 < 16) {
            *(float2*)&g_logits[(size_t)r0 * 16 + c0]       = make_float2(acc[ni].x, acc[ni].y);
            *(float2*)&g_logits[(size_t)(r0 + 8) * 16 + c0] = make_float2(acc[ni].z, acc[ni].w);
        } else {
            int c = c0 - 16;
            *(float2*)&g_q[(size_t)r0 * 64 + c]       = make_float2(acc[ni].x, acc[ni].y);
            *(float2*)&g_q[(size_t)(r0 + 8) * 64 + c] = make_float2(acc[ni].z, acc[ni].w);
        }
    }
}

// ---------------- K2: top-2 + softmax + list fill -----------------------------
__global__ void k_topk_fill() {
    int tok = blockIdx.x * 256 + threadIdx.x;
    if (tok >= TOKN) return;
    float lg[16];
#pragma unroll
    for (int c = 0; c < 16; c++) lg[c] = g_logits[(size_t)tok * 16 + c];
    float v0 = -1e30f, v1 = -1e30f; int i0 = 0, i1 = 0;
#pragma unroll
    for (int c = 0; c < 16; c++) {
        float l = lg[c];
        if (l > v0) { v1 = v0; i1 = i0; v0 = l; i0 = c; }
        else if (l > v1) { v1 = l; i1 = c; }
    }
    float s = 0.0f, w[16];
#pragma unroll
    for (int c = 0; c < 16; c++) { float e = __expf(lg[c] - v0); w[c] = e; s += e; }
    float rs = 1.0f / s;
#pragma unroll
    for (int c = 0; c < 16; c++) g_w[(size_t)tok * 16 + c] = w[c] * rs;
    g_sel[tok * 2 + 0] = i0;
    g_sel[tok * 2 + 1] = i1;
    int p0 = atomicAdd(&g_cursor[i0], 1); g_list[p0] = (unsigned)(tok * 2);
    int p1 = atomicAdd(&g_cursor[i1], 1); g_list[p1] = (unsigned)(tok * 2 + 1);
}

// ---------------- K3: grouped bf16 3-split GEMM, cp.async pipelined ----------
// Tile M=128 x N=192, KC=16 per stage, 64 stages, 2-stage double buffer.
// 8 warps = 2(M) x 4(N); warp tile 64x48.
// SMEM per buf (uint4): As0[8][32] | As1[8][32] | Bs[24][32]  (20 KB)
#define SM_AS1 256
#define SM_BS  512
#define SM_BUF 1280
__global__ __launch_bounds__(256) void k_ggemm(const float* __restrict__ x) {
    __shared__ __align__(16) uint4 SM[2 * SM_BUF];   // 40 KB
    __shared__ unsigned s_ent[128];

    const int tid = threadIdx.x;
    const int e = blockIdx.x >> 6;                   // 64 tiles (of 128) per expert
    const int lofs = e * CAP + (blockIdx.x & 63) * 128;
    if (tid < 128) s_ent[tid] = g_list[lofs + tid];
    __syncthreads();
    if (s_ent[0] == 0xFFFFFFFFu) return;

    const int warp = tid >> 5, lane = tid & 31;
    const int wm = warp >> 2, wn = warp & 3;

    // ---- staging precompute: 5 units/thread (A: u<512, B: u>=512) ----
    const uint4* srcb[5];
    uint32_t dsto[5];
#pragma unroll
    for (int i = 0; i < 5; i++) {
        int u = tid + i * 256;
        if (u < 512) {
            int r = u >> 2, j = u & 3;
            unsigned ent = s_ent[r];
            unsigned tok = (ent != 0xFFFFFFFFu) ? (ent >> 1) : 0u;
            srcb[i] = &g_xpack[(size_t)tok * 256 + j];
            int rl = r & 15;
            int idx = ((rl >= 8) ? SM_AS1 : 0) + (r >> 4) * 32 + 4 * (rl & 7) + j;
            dsto[i] = (uint32_t)__cvta_generic_to_shared(&SM[idx]);
        } else {
            int v = u - 512;
            int n = v >> 2, j = v & 3;
            srcb[i] = &g_wpack[((size_t)e * 192 + n) * 256 + j];
            int idx = SM_BS + (n >> 3) * 32 + 4 * (n & 7) + j;
            dsto[i] = (uint32_t)__cvta_generic_to_shared(&SM[idx]);
        }
    }

    float4 acc[4][6];
#pragma unroll
    for (int i = 0; i < 4; i++)
#pragma unroll
        for (int j = 0; j < 6; j++) acc[i][j] = make_float4(0.f, 0.f, 0.f, 0.f);

    // prologue: stage kts=0 into buf 0
#pragma unroll
    for (int i = 0; i < 5; i++) cpa16(dsto[i], srcb[i]);
    cpa_commit();

    for (int kts = 0; kts < NKTI; kts++) {
        const int buf = kts & 1;
        if (kts + 1 < NKTI) {
            uint32_t bofs = (uint32_t)((buf ^ 1) * SM_BUF * 16);
#pragma unroll
            for (int i = 0; i < 5; i++) cpa16(dsto[i] + bofs, srcb[i] + (size_t)(kts + 1) * 4);
            cpa_commit();
            cpa_wait<1>();
        } else {
            cpa_wait<0>();
        }
        __syncthreads();

        const uint4* B0 = &SM[buf * SM_BUF];
#pragma unroll
        for (int mh = 0; mh < 2; mh++) {
            uint32_t ah[2][4], al[2][4];
#pragma unroll
            for (int mi = 0; mi < 2; mi++) {
                int mt = wm * 4 + mh * 2 + mi;
                uint4 q0 = B0[mt * 32 + lane];
                uint4 q1 = B0[SM_AS1 + mt * 32 + lane];
                ah[mi][0] = q0.x; ah[mi][1] = q1.x; ah[mi][2] = q0.y; ah[mi][3] = q1.y;
                al[mi][0] = q0.z; al[mi][1] = q1.z; al[mi][2] = q0.w; al[mi][3] = q1.w;
            }
#pragma unroll
            for (int ni = 0; ni < 6; ni++) {
                uint4 qb = B0[SM_BS + (wn * 6 + ni) * 32 + lane];
#pragma unroll
                for (int mi = 0; mi < 2; mi++) {
                    float4 &d = acc[mh * 2 + mi][ni];
                    mma_bf16(d, ah[mi][0], ah[mi][1], ah[mi][2], ah[mi][3], qb.x, qb.y); // hi*hi
                    mma_bf16(d, ah[mi][0], ah[mi][1], ah[mi][2], ah[mi][3], qb.z, qb.w); // hi*lo
                    mma_bf16(d, al[mi][0], al[mi][1], al[mi][2], al[mi][3], qb.x, qb.y); // lo*hi
                }
            }
        }
        __syncthreads();
    }

    // epilogue: scatter
#pragma unroll
    for (int mq = 0; mq < 4; mq++) {
        int mt = wm * 4 + mq;
        int r0 = mt * 16 + (lane >> 2);
        unsigned e0 = s_ent[r0], e1 = s_ent[r0 + 8];
#pragma unroll
        for (int ni = 0; ni < 6; ni++) {
            int c0 = wn * 48 + ni * 8 + ((lane & 3) << 1);
            if (e0 != 0xFFFFFFFFu)
                *(float2*)&g_selout[(size_t)e0 * 192 + c0] = make_float2(acc[mq][ni].x, acc[mq][ni].y);
            if (e1 != 0xFFFFFFFFu)
                *(float2*)&g_selout[(size_t)e1 * 192 + c0] = make_float2(acc[mq][ni].z, acc[mq][ni].w);
        }
    }
}

// ---------------- K4: recurrent scan (1 bar/step + prefetch) -----------------
__global__ __launch_bounds__(64) void k_scan(const float* __restrict__ b_beta,
                                             float* __restrict__ out) {
    const int bc = blockIdx.x;
    const int b = bc >> 4, c = bc & 15;
    const int tid = threadIdx.x;

    float S[64];
#pragma unroll
    for (int j = 0; j < 64; j++) S[j] = 0.0f;
    const float bb = b_beta[c * 64 + tid];

    __shared__ float sq[2][64];
    __shared__ float skk[2][64];

    // prefetch t = 0
    int tok = b;
    float qv = g_q[(size_t)tok * 64 + tid];
    int2 sel = *(const int2*)&g_sel[tok * 2];
    float wv = g_w[(size_t)tok * 16 + c];
    int slot = (sel.x == c) ? 0 : ((sel.y == c) ? 1 : -1);
    float kkv = 0.f, vvv = 0.f, bpv = 0.f;
    if (slot >= 0) {
        const float* p = g_selout + ((size_t)tok * 2 + slot) * 192;
        kkv = p[tid]; vvv = p[64 + tid]; bpv = p[128 + tid];
    }

    for (int t = 0; t < TT; t++) {
        const int p = t & 1;
        sq[p][tid] = qv;
        skk[p][tid] = kkv;
        const int slot_c = slot;
        const float vv_c = vvv, bp_c = bpv, w_c = wv;
        const int tok_c = t * BB + b;
        __syncthreads();

        // prefetch t+1 (loads fly during compute)
        if (t + 1 < TT) {
            int tn = (t + 1) * BB + b;
            qv = g_q[(size_t)tn * 64 + tid];
            sel = *(const int2*)&g_sel[tn * 2];
            wv = g_w[(size_t)tn * 16 + c];
            slot = (sel.x == c) ? 0 : ((sel.y == c) ? 1 : -1);
            if (slot >= 0) {
                const float* pp = g_selout + ((size_t)tn * 2 + slot) * 192;
                kkv = pp[tid]; vvv = pp[64 + tid]; bpv = pp[128 + tid];
            }
        }

        if (slot_c >= 0) {   // CTA-uniform
            float k0 = skk[p][tid], k1 = skk[p][tid ^ 32];
            float ps = fmaf(k0, k0, k1 * k1);
#pragma unroll
            for (int o = 16; o; o >>= 1) ps += __shfl_xor_sync(0xffffffffu, ps, o);
            float rn = fast_rcp(sqrtf(ps) + 1e-6f);
            float r0 = 0.f, r1 = 0.f, r2 = 0.f, r3 = 0.f;
            const float* kk = skk[p];
#pragma unroll
            for (int j = 0; j < 64; j += 4) {
                r0 = fmaf(S[j+0], kk[j+0], r0);
                r1 = fmaf(S[j+1], kk[j+1], r1);
                r2 = fmaf(S[j+2], kk[j+2], r2);
                r3 = fmaf(S[j+3], kk[j+3], r3);
            }
            float delta = vv_c - ((r0 + r1) + (r2 + r3)) * rn;
            float beta = fsig(bp_c + bb);
            float sc = delta * rn;
#pragma unroll
            for (int j = 0; j < 64; j++)
                S[j] = ftanh(fmaf(beta, S[j], sc * kk[j]));
        }
        float a0 = 0.f, a1 = 0.f, a2 = 0.f, a3 = 0.f;
        const float* q = sq[p];
#pragma unroll
        for (int j = 0; j < 64; j += 4) {
            a0 = fmaf(S[j+0], q[j+0], a0);
            a1 = fmaf(S[j+1], q[j+1], a1);
            a2 = fmaf(S[j+2], q[j+2], a2);
            a3 = fmaf(S[j+3], q[j+3], a3);
        }
        float sv = (a0 + a1) + (a2 + a3);
        g_partial[((size_t)tok_c * 16 + c) * 64 + tid] = w_c * sv * sv * fsig(sv);
    }
    float* Sf = out + OUT_OFF;
    size_t base = (((size_t)b * 16 + c) * 64 + tid) * 64;
#pragma unroll
    for (int j = 0; j < 64; j++) Sf[base + j] = S[j];
}

// ---------------- K5: reduce over blocks -> outputs --------------------------
__global__ void k_reduce(float* __restrict__ out) {
    int idx = blockIdx.x * 256 + threadIdx.x;
    int tok = idx >> 6, i = idx & 63;
    float s = 0.0f;
#pragma unroll
    for (int c = 0; c < 16; c++)
        s += g_partial[((size_t)tok * 16 + c) * 64 + i];
    out[idx] = s;
}

// ---------------- launch -----------------------------------------------------
extern "C" void kernel_launch(void* const* d_in, const int* in_sizes, int n_in,
                              void* d_out, int out_size) {
    const float* x    = (const float*)d_in[0];
    const float* Wr   = (const float*)d_in[1];
    const float* Wkv  = (const float*)d_in[2];
    const float* Wb   = (const float*)d_in[3];
    const float* bb   = (const float*)d_in[4];
    const float* Wq   = (const float*)d_in[5];
    float* out = (float*)d_out;
    (void)in_sizes; (void)n_in; (void)out_size;

    const int prep_grid = TOKN + NBK * 192 + (NLIST + 255) / 256;  // 36352
    k_prep<<<prep_grid, 256>>>(x, Wkv, Wb);
    k_rq_mma<<<TOKN / 64, 256>>>(x, Wr, Wq);
    k_topk_fill<<<TOKN / 256, 256>>>();
    k_ggemm<<<NBK * (CAP / 128), 256>>>(x);
    k_scan<<<BB * NBK, 64>>>(bb, out);
    k_reduce<<<(TOKN * 64) / 256, 256>>>(out);
}

// round 6
// speedup vs baseline: 1.4874x; 1.4874x over previous
#include <cuda_runtime.h>
#include <cuda_bf16.h>
#include <math.h>
#include <stdint.h>

#define TT   512
#define BB   64
#define DD   1024
#define NBK  16
#define TOKN (TT*BB)                 // 32768
#define CAP  8192
#define NLIST (NBK*CAP)
#define OUT_OFF ((size_t)TOKN*64)
#define NKTI (DD/16)                 // 64 k-stages of 16

// ---------------- scratch ---------------------------------------------------
__device__ float    g_logits[TOKN*NBK];
__device__ float    g_q[(size_t)TOKN*64];
__device__ float    g_w[TOKN*NBK];
__device__ int      g_sel[TOKN*2];
__device__ float    g_selout[(size_t)TOKN*2*192];
__device__ float    g_partial[(size_t)TOKN*NBK*64];
__device__ unsigned g_list[NLIST];
__device__ int      g_cursor[NBK];
// W prepack only (12.6 MB): unit (row R, kti, j) = (h_b0, h_b1, l_b0, l_b1)
__device__ uint4    g_wpack[(size_t)NBK*192*256];

// ---------------- fast math --------------------------------------------------
__device__ __forceinline__ float ex2a(float x){ float r; asm("ex2.approx.f32 %0,%1;":"=f"(r):"f"(x)); return r; }
__device__ __forceinline__ float rcpa(float x){ float r; asm("rcp.approx.f32 %0,%1;":"=f"(r):"f"(x)); return r; }
__device__ __forceinline__ float fast_rcp(float z){ float y = rcpa(z); return y * fmaf(-z, y, 2.0f); }
__device__ __forceinline__ float fsig(float x){ float E = ex2a(-1.44269504f * x); return fast_rcp(1.0f + E); }
__device__ __forceinline__ float ftanh(float x){ float E = ex2a(2.88539008f * x); return fmaf(-2.0f, fast_rcp(1.0f + E), 1.0f); }

__device__ __forceinline__ uint32_t f2tf(float f){ uint32_t r; asm("cvt.rna.tf32.f32 %0,%1;":"=r"(r):"f"(f)); return r; }
__device__ __forceinline__ uint32_t bf16r(float f){ uint16_t r; asm("cvt.rn.bf16.f32 %0,%1;":"=h"(r):"f"(f)); return (uint32_t)r; }
__device__ __forceinline__ void split_pack(float a, float b, uint32_t &hi, uint32_t &lo){
    uint32_t ha = bf16r(a), hb = bf16r(b);
    float ra = a - __uint_as_float(ha << 16);
    float rb = b - __uint_as_float(hb << 16);
    hi = ha | (hb << 16);
    lo = bf16r(ra) | (bf16r(rb) << 16);
}

__device__ __forceinline__ void mma_tf32(float4 &d, const uint4 &a, const uint2 &b){
    asm volatile("mma.sync.aligned.m16n8k8.row.col.f32.tf32.tf32.f32 "
                 "{%0,%1,%2,%3},{%4,%5,%6,%7},{%8,%9},{%0,%1,%2,%3};"
                 : "+f"(d.x), "+f"(d.y), "+f"(d.z), "+f"(d.w)
                 : "r"(a.x), "r"(a.y), "r"(a.z), "r"(a.w), "r"(b.x), "r"(b.y));
}
__device__ __forceinline__ void mma_bf16(float4 &d, uint32_t a0, uint32_t a1, uint32_t a2, uint32_t a3,
                                         uint32_t b0, uint32_t b1){
    asm volatile("mma.sync.aligned.m16n8k16.row.col.f32.bf16.bf16.f32 "
                 "{%0,%1,%2,%3},{%4,%5,%6,%7},{%8,%9},{%0,%1,%2,%3};"
                 : "+f"(d.x), "+f"(d.y), "+f"(d.z), "+f"(d.w)
                 : "r"(a0), "r"(a1), "r"(a2), "r"(a3), "r"(b0), "r"(b1));
}

__device__ __forceinline__ void cpa16(uint32_t dst, const void* src){
    asm volatile("cp.async.cg.shared.global [%0], [%1], 16;\n" :: "r"(dst), "l"(src));
}
__device__ __forceinline__ void cpa_commit(){ asm volatile("cp.async.commit_group;\n"); }
template<int N> __device__ __forceinline__ void cpa_wait(){ asm volatile("cp.async.wait_group %0;\n"::"n"(N)); }

// ---------------- K0: prep — W split-pack + list init ------------------------
// blocks [0, 3072): W rows; [3072, 3584): list/cursor init
__global__ __launch_bounds__(256) void k_prep(const float* __restrict__ Wkv,
                                              const float* __restrict__ Wbeta) {
    const int bid = blockIdx.x, tid = threadIdx.x;
    if (bid < NBK * 192) {
        const int kti = tid >> 2, j = tid & 3;
        int e = bid / 192, n = bid % 192;
        const float* base = (n < 128) ? (Wkv + ((size_t)e * 128 + n) * DD)
                                      : (Wbeta + ((size_t)e * 64 + (n - 128)) * DD);
        const float* src = base + kti * 16 + 2 * j;
        float2 v0 = *(const float2*)src;
        float2 v1 = *(const float2*)(src + 8);
        uint32_t h0, l0, h1, l1;
        split_pack(v0.x, v0.y, h0, l0);
        split_pack(v1.x, v1.y, h1, l1);
        g_wpack[(size_t)bid * 256 + tid] = make_uint4(h0, h1, l0, l1);
    } else {
        int i = (bid - NBK * 192) * 256 + tid;
        if (i < NLIST) g_list[i] = 0xFFFFFFFFu;
        if (i < NBK)   g_cursor[i] = i * CAP;
    }
}

// ---------------- K1: router+q GEMM via tf32 3-split mma ---------------------
__global__ __launch_bounds__(256) void k_rq_mma(const float* __restrict__ x,
                                                const float* __restrict__ Wr,
                                                const float* __restrict__ Wq) {
    __shared__ uint32_t Ah[4*2*32*4], Al[4*2*32*4];
    __shared__ uint32_t Bh[10*2*32*2], Bl[10*2*32*2];

    const int tid = threadIdx.x;
    const int row0 = blockIdx.x * 64;
    const int warp = tid >> 5, lane = tid & 31;
    const int wm = warp >> 1, wn = warp & 1;

    float4 acc[5];
#pragma unroll
    for (int j = 0; j < 5; j++) acc[j] = make_float4(0.f, 0.f, 0.f, 0.f);

    const int xrow = tid >> 2, xk0 = (tid & 3) * 4;
    const float* xp = x + (size_t)(row0 + xrow) * DD + xk0;
    const int xs = xk0 >> 3;
    const int xreg = ((xk0 & 4) ? 2 : 0) + (((xrow & 15) >= 8) ? 1 : 0);
    const int xbase = ((((xrow >> 4) * 2 + xs) * 32 + ((xrow & 7) << 2)) << 2) + xreg;

    for (int kt = 0; kt < DD; kt += 16) {
        {
            float4 v = *(const float4*)(xp + kt);
            float vv[4] = {v.x, v.y, v.z, v.w};
#pragma unroll
            for (int j = 0; j < 4; j++) {
                uint32_t h = f2tf(vv[j]);
                Ah[xbase + (j << 2)] = h;
                Al[xbase + (j << 2)] = f2tf(vv[j] - __uint_as_float(h));
            }
        }
#pragma unroll
        for (int it = 0; it < 2; it++) {
            int fi = tid + it * 256;
            if (fi < 320) {
                int row = fi >> 2, k0 = (fi & 3) * 4;
                const float* wp = (row < 16) ? (Wr + (size_t)row * DD)
                                             : (Wq + (size_t)(row - 16) * DD);
                float4 v = *(const float4*)(wp + kt + k0);
                int s = k0 >> 3, reg = (k0 & 4) ? 1 : 0;
                int base = ((((row >> 3) * 2 + s) * 32 + ((row & 7) << 2)) << 1) + reg;
                float vv[4] = {v.x, v.y, v.z, v.w};
#pragma unroll
                for (int j = 0; j < 4; j++) {
                    uint32_t h = f2tf(vv[j]);
                    Bh[base + (j << 1)] = h;
                    Bl[base + (j << 1)] = f2tf(vv[j] - __uint_as_float(h));
                }
            }
        }
        __syncthreads();
#pragma unroll
        for (int s = 0; s < 2; s++) {
            int aidx = (((wm * 2 + s) * 32 + lane) << 2);
            uint4 ah = *(const uint4*)&Ah[aidx];
            uint4 al = *(const uint4*)&Al[aidx];
#pragma unroll
            for (int ni = 0; ni < 5; ni++) {
                int bidx = ((((wn * 5 + ni) * 2 + s) * 32 + lane) << 1);
                uint2 bh = *(const uint2*)&Bh[bidx];
                uint2 bl = *(const uint2*)&Bl[bidx];
                mma_tf32(acc[ni], ah, bh);
                mma_tf32(acc[ni], ah, bl);
                mma_tf32(acc[ni], al, bh);
            }
        }
        __syncthreads();
    }
    int r0 = row0 + wm * 16 + (lane >> 2);
#pragma unroll
    for (int ni = 0; ni < 5; ni++) {
        int c0 = wn * 40 + ni * 8 + ((lane & 3) << 1);
        if (c0 < 16) {
            *(float2*)&g_logits[(size_t)r0 * 16 + c0]       = make_float2(acc[ni].x, acc[ni].y);
            *(float2*)&g_logits[(size_t)(r0 + 8) * 16 + c0] = make_float2(acc[ni].z, acc[ni].w);
        } else {
            int c = c0 - 16;
            *(float2*)&g_q[(size_t)r0 * 64 + c]       = make_float2(acc[ni].x, acc[ni].y);
            *(float2*)&g_q[(size_t)(r0 + 8) * 64 + c] = make_float2(acc[ni].z, acc[ni].w);
        }
    }
}

// ---------------- K2: top-2 + softmax + list fill -----------------------------
__global__ void k_topk_fill() {
    int tok = blockIdx.x * 256 + threadIdx.x;
    if (tok >= TOKN) return;
    float lg[16];
#pragma unroll
    for (int c = 0; c < 16; c++) lg[c] = g_logits[(size_t)tok * 16 + c];
    float v0 = -1e30f, v1 = -1e30f; int i0 = 0, i1 = 0;
#pragma unroll
    for (int c = 0; c < 16; c++) {
        float l = lg[c];
        if (l > v0) { v1 = v0; i1 = i0; v0 = l; i0 = c; }
        else if (l > v1) { v1 = l; i1 = c; }
    }
    float s = 0.0f, w[16];
#pragma unroll
    for (int c = 0; c < 16; c++) { float e = __expf(lg[c] - v0); w[c] = e; s += e; }
    float rs = 1.0f / s;
#pragma unroll
    for (int c = 0; c < 16; c++) g_w[(size_t)tok * 16 + c] = w[c] * rs;
    g_sel[tok * 2 + 0] = i0;
    g_sel[tok * 2 + 1] = i1;
    int p0 = atomicAdd(&g_cursor[i0], 1); g_list[p0] = (unsigned)(tok * 2);
    int p1 = atomicAdd(&g_cursor[i1], 1); g_list[p1] = (unsigned)(tok * 2 + 1);
}

// ---------------- K3: grouped bf16 3-split GEMM ------------------------------
// Tile M=64 x N=192, 64 stages of KC=16, double-buffered (1 bar/stage).
// A (x) converted in-loop; B (W) cp.async from prepack. 8 warps = 2Mx4N.
__global__ __launch_bounds__(256, 2) void k_ggemm(const float* __restrict__ x) {
    __shared__ __align__(16) uint4 SMA[2][4 * 2 * 32];   //  8 KB: [buf][mt][hl][lane]
    __shared__ __align__(16) uint4 SMB[2][24 * 32];      // 24 KB: [buf][nt][lane]
    __shared__ unsigned s_ent[64];

    const int tid = threadIdx.x;
    const int e = blockIdx.x >> 7;                       // 128 tiles per expert
    const int lofs = e * CAP + (blockIdx.x & 127) * 64;
    if (tid < 64) s_ent[tid] = g_list[lofs + tid];
    __syncthreads();
    if (s_ent[0] == 0xFFFFFFFFu) return;

    const int warp = tid >> 5, lane = tid & 31;
    const int wm = warp >> 2, wn = warp & 3;

    // ---- A staging assignment: thread = (mt, rlow, j); rows r, r+8; k=2j,2j+1
    const int a_mt = tid >> 6, a_rlow = (tid >> 3) & 7, a_j = tid & 7;
    const int a_lane = a_rlow * 4 + (a_j & 3);
    const int a_reg  = (a_j >= 4) ? 2 : 0;
    const float* a_p0;
    const float* a_p1;
    {
        unsigned e0 = s_ent[a_mt * 16 + a_rlow];
        unsigned e1 = s_ent[a_mt * 16 + a_rlow + 8];
        a_p0 = (e0 != 0xFFFFFFFFu) ? (x + (size_t)(e0 >> 1) * DD + 2 * a_j) : nullptr;
        a_p1 = (e1 != 0xFFFFFFFFu) ? (x + (size_t)(e1 >> 1) * DD + 2 * a_j) : nullptr;
    }
    uint32_t a_hi_addr = (uint32_t)__cvta_generic_to_shared(
        &((uint32_t*)&SMA[0][(a_mt * 2 + 0) * 32 + a_lane])[a_reg]);
    uint32_t a_lo_addr = (uint32_t)__cvta_generic_to_shared(
        &((uint32_t*)&SMA[0][(a_mt * 2 + 1) * 32 + a_lane])[a_reg]);

    // ---- B staging: 3 cp.async units/thread ----
    const uint4* b_src[3];
    uint32_t b_dst[3];
#pragma unroll
    for (int i = 0; i < 3; i++) {
        int u = tid + i * 256;
        int n = u >> 2, j = u & 3;
        b_src[i] = &g_wpack[((size_t)e * 192 + n) * 256 + j];
        b_dst[i] = (uint32_t)__cvta_generic_to_shared(&SMB[0][(n >> 3) * 32 + (n & 7) * 4 + j]);
    }

    float4 acc[2][6];
#pragma unroll
    for (int i = 0; i < 2; i++)
#pragma unroll
        for (int j = 0; j < 6; j++) acc[i][j] = make_float4(0.f, 0.f, 0.f, 0.f);

    // ---- prologue: stage 0 into buf 0 ----
    {
        float2 v0 = make_float2(0.f, 0.f), v1 = v0;
        if (a_p0) v0 = *(const float2*)a_p0;
        if (a_p1) v1 = *(const float2*)a_p1;
        uint32_t h0, l0, h1, l1;
        split_pack(v0.x, v0.y, h0, l0);
        split_pack(v1.x, v1.y, h1, l1);
        asm volatile("st.shared.v2.u32 [%0], {%1,%2};" :: "r"(a_hi_addr), "r"(h0), "r"(h1));
        asm volatile("st.shared.v2.u32 [%0], {%1,%2};" :: "r"(a_lo_addr), "r"(l0), "r"(l1));
#pragma unroll
        for (int i = 0; i < 3; i++) cpa16(b_dst[i], b_src[i]);
        cpa_commit();
    }

    const uint32_t ABUF = sizeof(uint4) * 4 * 2 * 32;    // 4 KB
    const uint32_t BBUF = sizeof(uint4) * 24 * 32;       // 12 KB

    for (int kts = 0; kts < NKTI; kts++) {
        const int buf = kts & 1;
        // 1) issue A-next LDGs (fly under wait + compute)
        float2 va0 = make_float2(0.f, 0.f), va1 = va0;
        const bool more = (kts + 1 < NKTI);
        if (more) {
            if (a_p0) va0 = *(const float2*)(a_p0 + (kts + 1) * 16);
            if (a_p1) va1 = *(const float2*)(a_p1 + (kts + 1) * 16);
        }
        // 2) wait current B, publish current A
        cpa_wait<0>();
        __syncthreads();
        // 3) issue B-next cp.async into other buffer
        if (more) {
            uint32_t bo = (buf ^ 1) * BBUF;
#pragma unroll
            for (int i = 0; i < 3; i++) cpa16(b_dst[i] + bo, b_src[i] + (size_t)(kts + 1) * 4);
            cpa_commit();
        }
        // 4) compute on current buffer
        {
            const uint4* A0 = SMA[buf];
            const uint4* B0 = SMB[buf];
            uint4 qa_h[2], qa_l[2];
#pragma unroll
            for (int mi = 0; mi < 2; mi++) {
                int mt = wm * 2 + mi;
                qa_h[mi] = A0[(mt * 2 + 0) * 32 + lane];
                qa_l[mi] = A0[(mt * 2 + 1) * 32 + lane];
            }
#pragma unroll
            for (int ni = 0; ni < 6; ni++) {
                uint4 qb = B0[(wn * 6 + ni) * 32 + lane];
#pragma unroll
                for (int mi = 0; mi < 2; mi++) {
                    float4 &d = acc[mi][ni];
                    mma_bf16(d, qa_h[mi].x, qa_h[mi].y, qa_h[mi].z, qa_h[mi].w, qb.x, qb.y); // hi*hi
                    mma_bf16(d, qa_h[mi].x, qa_h[mi].y, qa_h[mi].z, qa_h[mi].w, qb.z, qb.w); // hi*lo
                    mma_bf16(d, qa_l[mi].x, qa_l[mi].y, qa_l[mi].z, qa_l[mi].w, qb.x, qb.y); // lo*hi
                }
            }
        }
        // 5) stage A-next into other buffer (published by next iteration's barrier)
        if (more) {
            uint32_t h0, l0, h1, l1;
            split_pack(va0.x, va0.y, h0, l0);
            split_pack(va1.x, va1.y, h1, l1);
            uint32_t ao = (buf ^ 1) * ABUF;
            asm volatile("st.shared.v2.u32 [%0], {%1,%2};" :: "r"(a_hi_addr + ao), "r"(h0), "r"(h1));
            asm volatile("st.shared.v2.u32 [%0], {%1,%2};" :: "r"(a_lo_addr + ao), "r"(l0), "r"(l1));
        }
    }

    // epilogue: scatter
#pragma unroll
    for (int mi = 0; mi < 2; mi++) {
        int r0 = (wm * 2 + mi) * 16 + (lane >> 2);
        unsigned e0 = s_ent[r0], e1 = s_ent[r0 + 8];
#pragma unroll
        for (int ni = 0; ni < 6; ni++) {
            int c0 = wn * 48 + ni * 8 + ((lane & 3) << 1);
            if (e0 != 0xFFFFFFFFu)
                *(float2*)&g_selout[(size_t)e0 * 192 + c0] = make_float2(acc[mi][ni].x, acc[mi][ni].y);
            if (e1 != 0xFFFFFFFFu)
                *(float2*)&g_selout[(size_t)e1 * 192 + c0] = make_float2(acc[mi][ni].z, acc[mi][ni].w);
        }
    }
}

// ---------------- K4: recurrent scan (1 bar/step + prefetch) -----------------
__global__ __launch_bounds__(64) void k_scan(const float* __restrict__ b_beta,
                                             float* __restrict__ out) {
    const int bc = blockIdx.x;
    const int b = bc >> 4, c = bc & 15;
    const int tid = threadIdx.x;

    float S[64];
#pragma unroll
    for (int j = 0; j < 64; j++) S[j] = 0.0f;
    const float bb = b_beta[c * 64 + tid];

    __shared__ float sq[2][64];
    __shared__ float skk[2][64];

    int tok = b;
    float qv = g_q[(size_t)tok * 64 + tid];
    int2 sel = *(const int2*)&g_sel[tok * 2];
    float wv = g_w[(size_t)tok * 16 + c];
    int slot = (sel.x == c) ? 0 : ((sel.y == c) ? 1 : -1);
    float kkv = 0.f, vvv = 0.f, bpv = 0.f;
    if (slot >= 0) {
        const float* p = g_selout + ((size_t)tok * 2 + slot) * 192;
        kkv = p[tid]; vvv = p[64 + tid]; bpv = p[128 + tid];
    }

    for (int t = 0; t < TT; t++) {
        const int p = t & 1;
        sq[p][tid] = qv;
        skk[p][tid] = kkv;
        const int slot_c = slot;
        const float vv_c = vvv, bp_c = bpv, w_c = wv;
        const int tok_c = t * BB + b;
        __syncthreads();

        if (t + 1 < TT) {
            int tn = (t + 1) * BB + b;
            qv = g_q[(size_t)tn * 64 + tid];
            sel = *(const int2*)&g_sel[tn * 2];
            wv = g_w[(size_t)tn * 16 + c];
            slot = (sel.x == c) ? 0 : ((sel.y == c) ? 1 : -1);
            if (slot >= 0) {
                const float* pp = g_selout + ((size_t)tn * 2 + slot) * 192;
                kkv = pp[tid]; vvv = pp[64 + tid]; bpv = pp[128 + tid];
            }
        }

        if (slot_c >= 0) {
            float k0 = skk[p][tid], k1 = skk[p][tid ^ 32];
            float ps = fmaf(k0, k0, k1 * k1);
#pragma unroll
            for (int o = 16; o; o >>= 1) ps += __shfl_xor_sync(0xffffffffu, ps, o);
            float rn = fast_rcp(sqrtf(ps) + 1e-6f);
            float r0 = 0.f, r1 = 0.f, r2 = 0.f, r3 = 0.f;
            const float* kk = skk[p];
#pragma unroll
            for (int j = 0; j < 64; j += 4) {
                r0 = fmaf(S[j+0], kk[j+0], r0);
                r1 = fmaf(S[j+1], kk[j+1], r1);
                r2 = fmaf(S[j+2], kk[j+2], r2);
                r3 = fmaf(S[j+3], kk[j+3], r3);
            }
            float delta = vv_c - ((r0 + r1) + (r2 + r3)) * rn;
            float beta = fsig(bp_c + bb);
            float sc = delta * rn;
#pragma unroll
            for (int j = 0; j < 64; j++)
                S[j] = ftanh(fmaf(beta, S[j], sc * kk[j]));
        }
        float a0 = 0.f, a1 = 0.f, a2 = 0.f, a3 = 0.f;
        const float* q = sq[p];
#pragma unroll
        for (int j = 0; j < 64; j += 4) {
            a0 = fmaf(S[j+0], q[j+0], a0);
            a1 = fmaf(S[j+1], q[j+1], a1);
            a2 = fmaf(S[j+2], q[j+2], a2);
            a3 = fmaf(S[j+3], q[j+3], a3);
        }
        float sv = (a0 + a1) + (a2 + a3);
        g_partial[((size_t)tok_c * 16 + c) * 64 + tid] = w_c * sv * sv * fsig(sv);
    }
    float* Sf = out + OUT_OFF;
    size_t base = (((size_t)b * 16 + c) * 64 + tid) * 64;
#pragma unroll
    for (int j = 0; j < 64; j++) Sf[base + j] = S[j];
}

// ---------------- K5: reduce over blocks -> outputs --------------------------
__global__ void k_reduce(float* __restrict__ out) {
    int idx = blockIdx.x * 256 + threadIdx.x;
    int tok = idx >> 6, i = idx & 63;
    float s = 0.0f;
#pragma unroll
    for (int c = 0; c < 16; c++)
        s += g_partial[((size_t)tok * 16 + c) * 64 + i];
    out[idx] = s;
}

// ---------------- launch -----------------------------------------------------
extern "C" void kernel_launch(void* const* d_in, const int* in_sizes, int n_in,
                              void* d_out, int out_size) {
    const float* x    = (const float*)d_in[0];
    const float* Wr   = (const float*)d_in[1];
    const float* Wkv  = (const float*)d_in[2];
    const float* Wb   = (const float*)d_in[3];
    const float* bb   = (const float*)d_in[4];
    const float* Wq   = (const float*)d_in[5];
    float* out = (float*)d_out;
    (void)in_sizes; (void)n_in; (void)out_size;

    const int prep_grid = NBK * 192 + (NLIST + 255) / 256;   // 3584
    k_prep<<<prep_grid, 256>>>(Wkv, Wb);
    k_rq_mma<<<TOKN / 64, 256>>>(x, Wr, Wq);
    k_topk_fill<<<TOKN / 256, 256>>>();
    k_ggemm<<<NBK * (CAP / 64), 256>>>(x);
    k_scan<<<BB * NBK, 64>>>(bb, out);
    k_reduce<<<(TOKN * 64) / 256, 256>>>(out);
}